// round 15
// baseline (speedup 1.0000x reference)
#include <cuda_runtime.h>
#include <cuda_fp16.h>
#include <cstdint>

#define B_ 512
#define N_ 512
#define M_ 512
#define T_ 100

// Scratch (device globals — no allocation at kernel_launch time)
__device__ __half g_S[(size_t)B_ * T_ * N_];   // [b][t][n], values ±1, fp16 (52.4 MB)
__device__ __half g_W[(size_t)M_ * N_];        // fp16 copy of weight

// ===========================================================================
// Threefry2x32-20, key (0,42), partitionable path: bits = o0 ^ o1, ctr=(0, i)
// Adds routed to IMAD (fma pipe) via runtime 'one' so ptxas can't fold.
// 4 of the 20 rotations are also routed to the fma pipe as IMAD.HI+IMAD.LO
// (bit-exact: rotl = (x<<d)|(x>>(32-d)) = lo + hi of x*2^d, disjoint bits)
// to balance the alu pipe (97% -> ~88%) against fma (40% -> ~86%).
// ===========================================================================
__device__ __forceinline__ uint32_t rotl32(uint32_t x, int d) {
    return __funnelshift_l(x, x, d);
}
__device__ __forceinline__ uint32_t addi(uint32_t a, uint32_t b, uint32_t one) {
    uint32_t r;
    asm("mad.lo.u32 %0, %1, %2, %3;" : "=r"(r) : "r"(a), "r"(one), "r"(b));
    return r;
}
__device__ __forceinline__ uint32_t rotl_imad(uint32_t x, uint32_t pow2d) {
    uint32_t hi, r;
    asm("mul.hi.u32 %0, %1, %2;" : "=r"(hi) : "r"(x), "r"(pow2d));
    asm("mad.lo.u32 %0, %1, %2, %3;" : "=r"(r) : "r"(x), "r"(pow2d), "r"(hi));
    return r;
}
#define TFR(r) { x0 = addi(x0, x1, one); x1 = rotl32(x1, r); x1 ^= x0; }
#define TFRI(r) { x0 = addi(x0, x1, one); x1 = rotl_imad(x1, 1u << (r)); x1 ^= x0; }
__device__ __forceinline__ uint32_t tf_bits(uint32_t ctr, uint32_t one) {
    const uint32_t k1 = 42u, k2 = 0x1BD11BF0u;   // 0x1BD11BDA ^ 0 ^ 42
    uint32_t x1 = ctr + k1;
    uint32_t x0 = x1;             // round 1: x0 = 0 + x1
    x1 = rotl32(x1, 13); x1 ^= x0;
    TFR(15) TFRI(26) TFR(6)
    x0 = addi(x0, k1, one); x1 = addi(x1, k2 + 1u, one);
    TFR(17) TFRI(29) TFR(16) TFR(24)
    x0 = addi(x0, k2, one); x1 = addi(x1, 0u + 2u, one);
    TFR(13) TFR(15) TFRI(26) TFR(6)
    /* x0 += k0 (0) */              x1 = addi(x1, k1 + 3u, one);
    TFR(17) TFR(29) TFR(16) TFR(24)
    x0 = addi(x0, k1, one); x1 = addi(x1, k2 + 4u, one);
    TFR(13) TFR(15) TFRI(26) TFR(6)
    x0 = addi(x0, k2, one); x1 = addi(x1, 0u + 5u, one);
    return x0 ^ x1;
}

// ---------------------------------------------------------------------------
// Sample generation. Integer Bernoulli: bits < (mu<<9)  ==  (bits>>9) < mu
// == u01(bits) < p   with mu = ceil(p * 2^23)  (exact for p in [0.5, 1)).
// ---------------------------------------------------------------------------
__global__ void gen_kernel(const float* __restrict__ input, uint32_t one) {
    int idx = blockIdx.x * blockDim.x + threadIdx.x;   // b*512+n
    int b = idx >> 9;
    int n = idx & 511;
    float p = 0.5f + 0.5f * input[idx];
    uint32_t mu = (uint32_t)ceilf(p * 8388608.0f);
    uint32_t mu9 = (mu >= 0x800000u) ? 0xFFFFFFFFu : (mu << 9);
    uint32_t jb = (uint32_t)idx * 100u;
    const __half POS = __float2half_rn(1.0f);
    const __half NEG = __float2half_rn(-1.0f);
    __half* sp = g_S + (size_t)b * T_ * N_ + n;
    #pragma unroll 4
    for (int t = 0; t < T_; t++) {
        uint32_t bits = tf_bits(jb + (uint32_t)t, one);
        sp[(size_t)t * N_] = (bits < mu9) ? POS : NEG;
    }
}

__global__ void wconv_kernel(const float* __restrict__ W) {
    int i = blockIdx.x * blockDim.x + threadIdx.x;
    if (i < M_ * N_) g_W[i] = __float2half_rn(W[i]);
}

// ===========================================================================
// Fused GEMM + erf + mean-over-t  (mma.sync + cp.async 3-stage pipeline).
// R10-proven config: Grid (M/128, B). Block 256 threads = 8 warps
// (2 row-warps x 4 col-warps, warp tile 64x32). C tile 128(t) x 128(m).
// K = 512 in 8 chunks of 64. Stage = A 16KB + B 16KB. 3 stages, 2 CTAs/SM.
// ===========================================================================
#define SMEM_SWZ(off) ((off) ^ (((off) >> 3) & 0x70))
#define STAGEB 32768
#define NSTAGE 3
#define NCHUNK 8
#define SMEM_GEMM (NSTAGE * STAGEB)   // 98304 B

__device__ __forceinline__ uint32_t smem_u32(const void* p) {
    uint32_t a;
    asm("{ .reg .u64 t; cvta.to.shared.u64 t, %1; cvt.u32.u64 %0, t; }" : "=r"(a) : "l"(p));
    return a;
}
__device__ __forceinline__ void cpasync16(uint32_t dst, const void* src, uint32_t srcsize) {
    asm volatile("cp.async.cg.shared.global [%0], [%1], 16, %2;"
                 :: "r"(dst), "l"(src), "r"(srcsize) : "memory");
}
__device__ __forceinline__ void cpcommit() {
    asm volatile("cp.async.commit_group;" ::: "memory");
}
template <int NPending>
__device__ __forceinline__ void cpwait() {
    asm volatile("cp.async.wait_group %0;" :: "n"(NPending) : "memory");
}
__device__ __forceinline__ void ldmx4(uint32_t& r0, uint32_t& r1, uint32_t& r2, uint32_t& r3, uint32_t addr) {
    asm volatile("ldmatrix.sync.aligned.m8n8.x4.shared.b16 {%0,%1,%2,%3}, [%4];"
                 : "=r"(r0), "=r"(r1), "=r"(r2), "=r"(r3) : "r"(addr));
}
__device__ __forceinline__ void mma16816(float* c, const uint32_t* a, const uint32_t* b) {
    asm volatile("mma.sync.aligned.m16n8k16.row.col.f32.f16.f16.f32 "
                 "{%0,%1,%2,%3}, {%4,%5,%6,%7}, {%8,%9}, {%0,%1,%2,%3};"
                 : "+f"(c[0]), "+f"(c[1]), "+f"(c[2]), "+f"(c[3])
                 : "r"(a[0]), "r"(a[1]), "r"(a[2]), "r"(a[3]), "r"(b[0]), "r"(b[1]));
}

// erf via degree-5 Taylor (2/sqrt(pi))(z - z^3/3 + z^5/10): abs err < 2e-6 for
// |z| <= 0.25 (z here is ~N(0, 0.04): 6-sigma inside). Guarded erff fallback.
__device__ __forceinline__ float erf_small(float z) {
    float t2 = z * z;
    float e = z * (1.12837917f + t2 * (-0.37612639f + t2 * 0.11283792f));
    if (t2 > 0.0625f) e = erff(z);
    return e;
}

__global__ void __launch_bounds__(256, 2)
gemm_kernel(const float* __restrict__ bias, float* __restrict__ out) {
    extern __shared__ char smem[];
    const uint32_t sbase = smem_u32(smem);

    const int b     = blockIdx.y;
    const int mtile = blockIdx.x * 128;
    const int tid   = threadIdx.x;
    const int lane  = tid & 31;
    const int wid   = tid >> 5;
    const int wr    = wid >> 2;        // warp row (0..1): rows wr*64..wr*64+63
    const int wc    = wid & 3;         // warp col (0..3): cols wc*32..wc*32+31
    const int g     = lane >> 2;
    const int tq    = lane & 3;

    const __half* Ab = g_S + (size_t)b * T_ * N_;
    const __half* Bb = g_W + (size_t)mtile * N_;

    // ---- per-thread cp.async mapping: 4 A-groups + 4 B-groups per chunk ----
    int ldRow[4], ldKg[4];
    uint32_t ldDst[4];
    #pragma unroll
    for (int i = 0; i < 4; i++) {
        int id = tid + i * 256;
        ldRow[i] = id >> 3;
        ldKg[i]  = id & 7;
        ldDst[i] = (uint32_t)SMEM_SWZ(ldRow[i] * 128 + ldKg[i] * 16);
    }

    // ---- accumulators initialized with bias ----
    float c[4][4][4];
    #pragma unroll
    for (int j = 0; j < 4; j++) {
        int col = mtile + wc * 32 + j * 8 + 2 * tq;
        float b0v = __ldg(bias + col);
        float b1v = __ldg(bias + col + 1);
        #pragma unroll
        for (int i = 0; i < 4; i++) {
            c[i][j][0] = b0v; c[i][j][1] = b1v; c[i][j][2] = b0v; c[i][j][3] = b1v;
        }
    }

    // ---- ldmatrix addressing: pre-swizzle base ub + per-fragment XOR mask
    //      x = (ub>>3)&0x70; per-k address = (ub + k*32) ^ x ----
    const int l16 = lane & 15;
    uint32_t aUb[4], aXm[4], bUb[2], bXm[2];
    #pragma unroll
    for (int i = 0; i < 4; i++) {
        uint32_t ub = (uint32_t)((wr * 64 + i * 16 + l16) * 128 + (lane >> 4) * 16);
        aUb[i] = ub; aXm[i] = (ub >> 3) & 0x70;
    }
    #pragma unroll
    for (int j = 0; j < 2; j++) {
        // B ldmx4 covering n16 x k16 (mapping verified in passing R12-R14):
        // row-in-16 = (lane&7)|((lane&16)>>1), kg = (lane>>3)&1
        uint32_t rin = (uint32_t)((lane & 7) | ((lane & 16) >> 1));
        uint32_t ub = (uint32_t)((wc * 32 + j * 16 + rin) * 128 + ((lane >> 3) & 1) * 16);
        bUb[j] = ub; bXm[j] = (ub >> 3) & 0x70;
    }

    // ---- stage loader ----
    auto load_chunk = [&](int chunk, int stage) {
        const uint32_t so = sbase + stage * STAGEB;
        #pragma unroll
        for (int i = 0; i < 4; i++) {          // A (zero-fill rows >= T)
            int row = ldRow[i];
            int rc = (row < T_) ? row : 0;
            cpasync16(so + ldDst[i],
                      Ab + (size_t)rc * N_ + chunk * 64 + ldKg[i] * 8,
                      (row < T_) ? 16u : 0u);
        }
        #pragma unroll
        for (int i = 0; i < 4; i++) {          // B
            cpasync16(so + 16384 + ldDst[i],
                      Bb + (size_t)ldRow[i] * N_ + chunk * 64 + ldKg[i] * 8,
                      16u);
        }
        cpcommit();
    };

    // ---- compute one 64-K chunk (6 LDSM -> 16 mma per k-step) ----
    auto compute_chunk = [&](int stage) {
        const uint32_t soff = sbase + (uint32_t)(stage * STAGEB);
        #pragma unroll
        for (int k = 0; k < 4; k++) {
            const uint32_t ko = (uint32_t)(k * 32);
            uint32_t af[4][4], bq[2][4];
            #pragma unroll
            for (int i = 0; i < 4; i++)
                ldmx4(af[i][0], af[i][1], af[i][2], af[i][3],
                      soff + ((aUb[i] + ko) ^ aXm[i]));
            #pragma unroll
            for (int j = 0; j < 2; j++)
                ldmx4(bq[j][0], bq[j][1], bq[j][2], bq[j][3],
                      soff + 16384 + ((bUb[j] + ko) ^ bXm[j]));
            #pragma unroll
            for (int i = 0; i < 4; i++) {
                // rows 112..127 (wr==1, i==3) are all zero padding — skip
                if (wr == 0 || i < 3) {
                    #pragma unroll
                    for (int j = 0; j < 4; j++)
                        mma16816(c[i][j], af[i], &bq[j >> 1][(j & 1) * 2]);
                }
            }
        }
    };

    // ---- prologue + pipelined main loop (1 barrier per chunk) ----
    load_chunk(0, 0);
    load_chunk(1, 1);
    #pragma unroll 1
    for (int ck = 0; ck < NCHUNK - 1; ck++) {
        cpwait<1>();
        __syncthreads();
        if (ck + 2 < NCHUNK) load_chunk(ck + 2, (ck + 2) % NSTAGE);
        compute_chunk(ck % NSTAGE);
    }
    cpwait<0>();
    __syncthreads();
    compute_chunk((NCHUNK - 1) % NSTAGE);
    __syncthreads();                       // before overlaying stage 0 with 'red'

    // ---- epilogue: erf(poly), mask t>=100 rows, reduce over t, mean ----
    float* red = (float*)smem;             // [2][128] overlay on stage 0
    const float ZS = 0.03125f;             // 1/sqrt(2*512)
    #pragma unroll
    for (int j = 0; j < 4; j++) {
        float s0 = 0.0f, s1 = 0.0f;
        #pragma unroll
        for (int i = 0; i < 4; i++) {
            int r0 = wr * 64 + i * 16 + g;
            int r1 = r0 + 8;
            if (r0 < T_) { s0 += erf_small(c[i][j][0] * ZS); s1 += erf_small(c[i][j][1] * ZS); }
            if (r1 < T_) { s0 += erf_small(c[i][j][2] * ZS); s1 += erf_small(c[i][j][3] * ZS); }
        }
        #pragma unroll
        for (int off = 16; off >= 4; off >>= 1) {
            s0 += __shfl_down_sync(0xffffffffu, s0, off);
            s1 += __shfl_down_sync(0xffffffffu, s1, off);
        }
        if (lane < 4) {
            int colL = wc * 32 + j * 8 + 2 * tq;
            red[wr * 128 + colL]     = s0;
            red[wr * 128 + colL + 1] = s1;
        }
    }
    __syncthreads();
    if (tid < 128) {
        float acc = red[tid] + red[128 + tid];
        out[(size_t)b * M_ + mtile + tid] = acc * 0.01f;   // mean over T=100
    }
}

// ---------------------------------------------------------------------------
// Serial launch (multi-stream overlap regressed twice: R11 +5us, R12 +42us).
// ---------------------------------------------------------------------------
extern "C" void kernel_launch(void* const* d_in, const int* in_sizes, int n_in,
                              void* d_out, int out_size) {
    const float* input  = (const float*)d_in[0];   // [512, 512]
    const float* weight = (const float*)d_in[1];   // [512, 512]
    const float* bias   = (const float*)d_in[2];   // [512]
    float* out = (float*)d_out;                    // [512, 512]

    cudaFuncSetAttribute(gemm_kernel, cudaFuncAttributeMaxDynamicSharedMemorySize, SMEM_GEMM);

    gen_kernel<<<1024, 256>>>(input, 1u);
    wconv_kernel<<<512, 512>>>(weight);
    gemm_kernel<<<dim3(4, 512), 256, SMEM_GEMM>>>(bias, out);
}

// round 16
// speedup vs baseline: 1.0268x; 1.0268x over previous
#include <cuda_runtime.h>
#include <cuda_fp16.h>
#include <cstdint>

#define B_ 512
#define N_ 512
#define M_ 512
#define T_ 100

// Scratch (device globals — no allocation at kernel_launch time)
__device__ __half g_S[(size_t)B_ * T_ * N_];   // [b][t][n], values ±1, fp16 (52.4 MB)
__device__ __half g_W[(size_t)M_ * N_];        // fp16 copy of weight

// ===========================================================================
// Threefry2x32-20, key (0,42), partitionable path: bits = o0 ^ o1, ctr=(0, i)
// Adds routed to IMAD (fma pipe) via runtime 'one' so ptxas can't fold.
// Rotations stay on SHF (alu): IMAD-rotl lengthened the serial chain and
// regressed R15 — gen is latency-sensitive, not purely throughput-bound.
// ===========================================================================
__device__ __forceinline__ uint32_t rotl32(uint32_t x, int d) {
    return __funnelshift_l(x, x, d);
}
__device__ __forceinline__ uint32_t addi(uint32_t a, uint32_t b, uint32_t one) {
    uint32_t r;
    asm("mad.lo.u32 %0, %1, %2, %3;" : "=r"(r) : "r"(a), "r"(one), "r"(b));
    return r;
}
#define TFR(r) { x0 = addi(x0, x1, one); x1 = rotl32(x1, r); x1 ^= x0; }
__device__ __forceinline__ uint32_t tf_bits(uint32_t ctr, uint32_t one) {
    const uint32_t k1 = 42u, k2 = 0x1BD11BF0u;   // 0x1BD11BDA ^ 0 ^ 42
    uint32_t x1 = ctr + k1;
    uint32_t x0 = x1;             // round 1: x0 = 0 + x1
    x1 = rotl32(x1, 13); x1 ^= x0;
    TFR(15) TFR(26) TFR(6)
    x0 = addi(x0, k1, one); x1 = addi(x1, k2 + 1u, one);
    TFR(17) TFR(29) TFR(16) TFR(24)
    x0 = addi(x0, k2, one); x1 = addi(x1, 0u + 2u, one);
    TFR(13) TFR(15) TFR(26) TFR(6)
    /* x0 += k0 (0) */              x1 = addi(x1, k1 + 3u, one);
    TFR(17) TFR(29) TFR(16) TFR(24)
    x0 = addi(x0, k1, one); x1 = addi(x1, k2 + 4u, one);
    TFR(13) TFR(15) TFR(26) TFR(6)
    x0 = addi(x0, k2, one); x1 = addi(x1, 0u + 5u, one);
    return x0 ^ x1;
}

// ---------------------------------------------------------------------------
// Sample generation. Integer Bernoulli: bits < (mu<<9)  ==  (bits>>9) < mu
// == u01(bits) < p   with mu = ceil(p * 2^23)  (exact for p in [0.5, 1)).
// ---------------------------------------------------------------------------
__global__ void gen_kernel(const float* __restrict__ input, uint32_t one) {
    int idx = blockIdx.x * blockDim.x + threadIdx.x;   // b*512+n
    int b = idx >> 9;
    int n = idx & 511;
    float p = 0.5f + 0.5f * input[idx];
    uint32_t mu = (uint32_t)ceilf(p * 8388608.0f);
    uint32_t mu9 = (mu >= 0x800000u) ? 0xFFFFFFFFu : (mu << 9);
    uint32_t jb = (uint32_t)idx * 100u;
    const __half POS = __float2half_rn(1.0f);
    const __half NEG = __float2half_rn(-1.0f);
    __half* sp = g_S + (size_t)b * T_ * N_ + n;
    #pragma unroll 4
    for (int t = 0; t < T_; t++) {
        uint32_t bits = tf_bits(jb + (uint32_t)t, one);
        sp[(size_t)t * N_] = (bits < mu9) ? POS : NEG;
    }
}

__global__ void wconv_kernel(const float* __restrict__ W) {
    int i = blockIdx.x * blockDim.x + threadIdx.x;
    if (i < M_ * N_) g_W[i] = __float2half_rn(W[i]);
}

// ===========================================================================
// Fused GEMM + erf + mean-over-t  (mma.sync + cp.async 3-stage pipeline).
// R10-proven config: Grid (M/128, B). Block 256 threads = 8 warps
// (2 row-warps x 4 col-warps, warp tile 64x32). C tile 128(t) x 128(m).
// K = 512 in 8 chunks of 64. Stage = A 16KB + B 16KB. 3 stages, 2 CTAs/SM.
// ===========================================================================
#define SMEM_SWZ(off) ((off) ^ (((off) >> 3) & 0x70))
#define STAGEB 32768
#define NSTAGE 3
#define NCHUNK 8
#define SMEM_GEMM (NSTAGE * STAGEB)   // 98304 B

__device__ __forceinline__ uint32_t smem_u32(const void* p) {
    uint32_t a;
    asm("{ .reg .u64 t; cvta.to.shared.u64 t, %1; cvt.u32.u64 %0, t; }" : "=r"(a) : "l"(p));
    return a;
}
__device__ __forceinline__ void cpasync16(uint32_t dst, const void* src, uint32_t srcsize) {
    asm volatile("cp.async.cg.shared.global [%0], [%1], 16, %2;"
                 :: "r"(dst), "l"(src), "r"(srcsize) : "memory");
}
__device__ __forceinline__ void cpcommit() {
    asm volatile("cp.async.commit_group;" ::: "memory");
}
template <int NPending>
__device__ __forceinline__ void cpwait() {
    asm volatile("cp.async.wait_group %0;" :: "n"(NPending) : "memory");
}
__device__ __forceinline__ void ldmx4(uint32_t& r0, uint32_t& r1, uint32_t& r2, uint32_t& r3, uint32_t addr) {
    asm volatile("ldmatrix.sync.aligned.m8n8.x4.shared.b16 {%0,%1,%2,%3}, [%4];"
                 : "=r"(r0), "=r"(r1), "=r"(r2), "=r"(r3) : "r"(addr));
}
__device__ __forceinline__ void mma16816(float* c, const uint32_t* a, const uint32_t* b) {
    asm volatile("mma.sync.aligned.m16n8k16.row.col.f32.f16.f16.f32 "
                 "{%0,%1,%2,%3}, {%4,%5,%6,%7}, {%8,%9}, {%0,%1,%2,%3};"
                 : "+f"(c[0]), "+f"(c[1]), "+f"(c[2]), "+f"(c[3])
                 : "r"(a[0]), "r"(a[1]), "r"(a[2]), "r"(a[3]), "r"(b[0]), "r"(b[1]));
}

// erf via degree-5 Taylor (2/sqrt(pi))(z - z^3/3 + z^5/10): abs err < 2e-6 for
// |z| <= 0.25 (z here is ~N(0, 0.04): 6-sigma inside). Guarded erff fallback.
__device__ __forceinline__ float erf_small(float z) {
    float t2 = z * z;
    float e = z * (1.12837917f + t2 * (-0.37612639f + t2 * 0.11283792f));
    if (t2 > 0.0625f) e = erff(z);
    return e;
}

__global__ void __launch_bounds__(256, 2)
gemm_kernel(const float* __restrict__ bias, float* __restrict__ out) {
    extern __shared__ char smem[];
    const uint32_t sbase = smem_u32(smem);

    const int b     = blockIdx.y;
    const int mtile = blockIdx.x * 128;
    const int tid   = threadIdx.x;
    const int lane  = tid & 31;
    const int wid   = tid >> 5;
    const int wr    = wid >> 2;        // warp row (0..1): rows wr*64..wr*64+63
    const int wc    = wid & 3;         // warp col (0..3): cols wc*32..wc*32+31
    const int g     = lane >> 2;
    const int tq    = lane & 3;

    const __half* Ab = g_S + (size_t)b * T_ * N_;
    const __half* Bb = g_W + (size_t)mtile * N_;

    // ---- per-thread cp.async mapping: 4 A-groups + 4 B-groups per chunk ----
    int ldRow[4], ldKg[4];
    uint32_t ldDst[4];
    #pragma unroll
    for (int i = 0; i < 4; i++) {
        int id = tid + i * 256;
        ldRow[i] = id >> 3;
        ldKg[i]  = id & 7;
        ldDst[i] = (uint32_t)SMEM_SWZ(ldRow[i] * 128 + ldKg[i] * 16);
    }

    // ---- stage loader ----
    auto load_chunk = [&](int chunk, int stage) {
        const uint32_t so = sbase + stage * STAGEB;
        #pragma unroll
        for (int i = 0; i < 4; i++) {          // A (zero-fill rows >= T)
            int row = ldRow[i];
            int rc = (row < T_) ? row : 0;
            cpasync16(so + ldDst[i],
                      Ab + (size_t)rc * N_ + chunk * 64 + ldKg[i] * 8,
                      (row < T_) ? 16u : 0u);
        }
        #pragma unroll
        for (int i = 0; i < 4; i++) {          // B
            cpasync16(so + 16384 + ldDst[i],
                      Bb + (size_t)ldRow[i] * N_ + chunk * 64 + ldKg[i] * 8,
                      16u);
        }
        cpcommit();
    };

    // ---- prologue FIRST: get the L2 round-trip in flight before setup ----
    load_chunk(0, 0);
    load_chunk(1, 1);

    // ---- accumulators initialized with bias (hides prologue latency) ----
    float c[4][4][4];
    #pragma unroll
    for (int j = 0; j < 4; j++) {
        int col = mtile + wc * 32 + j * 8 + 2 * tq;
        float b0v = __ldg(bias + col);
        float b1v = __ldg(bias + col + 1);
        #pragma unroll
        for (int i = 0; i < 4; i++) {
            c[i][j][0] = b0v; c[i][j][1] = b1v; c[i][j][2] = b0v; c[i][j][3] = b1v;
        }
    }

    // ---- ldmatrix addressing: pre-swizzle base ub + per-fragment XOR mask
    //      x = (ub>>3)&0x70; per-k address = (ub + k*32) ^ x ----
    const int l16 = lane & 15;
    uint32_t aUb[4], aXm[4], bUb[2], bXm[2];
    #pragma unroll
    for (int i = 0; i < 4; i++) {
        uint32_t ub = (uint32_t)((wr * 64 + i * 16 + l16) * 128 + (lane >> 4) * 16);
        aUb[i] = ub; aXm[i] = (ub >> 3) & 0x70;
    }
    #pragma unroll
    for (int j = 0; j < 2; j++) {
        // B ldmx4 covering n16 x k16 (mapping verified in passing R12-R15):
        // row-in-16 = (lane&7)|((lane&16)>>1), kg = (lane>>3)&1
        uint32_t rin = (uint32_t)((lane & 7) | ((lane & 16) >> 1));
        uint32_t ub = (uint32_t)((wc * 32 + j * 16 + rin) * 128 + ((lane >> 3) & 1) * 16);
        bUb[j] = ub; bXm[j] = (ub >> 3) & 0x70;
    }

    // ---- compute one 64-K chunk (6 LDSM -> 16 mma per k-step) ----
    auto compute_chunk = [&](int stage) {
        const uint32_t soff = sbase + (uint32_t)(stage * STAGEB);
        #pragma unroll
        for (int k = 0; k < 4; k++) {
            const uint32_t ko = (uint32_t)(k * 32);
            uint32_t af[4][4], bq[2][4];
            #pragma unroll
            for (int i = 0; i < 4; i++)
                ldmx4(af[i][0], af[i][1], af[i][2], af[i][3],
                      soff + ((aUb[i] + ko) ^ aXm[i]));
            #pragma unroll
            for (int j = 0; j < 2; j++)
                ldmx4(bq[j][0], bq[j][1], bq[j][2], bq[j][3],
                      soff + 16384 + ((bUb[j] + ko) ^ bXm[j]));
            #pragma unroll
            for (int i = 0; i < 4; i++) {
                // rows 112..127 (wr==1, i==3) are all zero padding — skip
                if (wr == 0 || i < 3) {
                    #pragma unroll
                    for (int j = 0; j < 4; j++)
                        mma16816(c[i][j], af[i], &bq[j >> 1][(j & 1) * 2]);
                }
            }
        }
    };

    // ---- pipelined main loop (1 barrier per chunk) ----
    #pragma unroll 1
    for (int ck = 0; ck < NCHUNK - 1; ck++) {
        cpwait<1>();
        __syncthreads();
        if (ck + 2 < NCHUNK) load_chunk(ck + 2, (ck + 2) % NSTAGE);
        compute_chunk(ck % NSTAGE);
    }
    cpwait<0>();
    __syncthreads();
    compute_chunk((NCHUNK - 1) % NSTAGE);
    __syncthreads();                       // before overlaying stage 0 with 'red'

    // ---- epilogue: erf(poly), mask t>=100 rows, reduce over t, mean ----
    float* red = (float*)smem;             // [2][128] overlay on stage 0
    const float ZS = 0.03125f;             // 1/sqrt(2*512)
    #pragma unroll
    for (int j = 0; j < 4; j++) {
        float s0 = 0.0f, s1 = 0.0f;
        #pragma unroll
        for (int i = 0; i < 4; i++) {
            int r0 = wr * 64 + i * 16 + g;
            int r1 = r0 + 8;
            if (r0 < T_) { s0 += erf_small(c[i][j][0] * ZS); s1 += erf_small(c[i][j][1] * ZS); }
            if (r1 < T_) { s0 += erf_small(c[i][j][2] * ZS); s1 += erf_small(c[i][j][3] * ZS); }
        }
        #pragma unroll
        for (int off = 16; off >= 4; off >>= 1) {
            s0 += __shfl_down_sync(0xffffffffu, s0, off);
            s1 += __shfl_down_sync(0xffffffffu, s1, off);
        }
        if (lane < 4) {
            int colL = wc * 32 + j * 8 + 2 * tq;
            red[wr * 128 + colL]     = s0;
            red[wr * 128 + colL + 1] = s1;
        }
    }
    __syncthreads();
    if (tid < 128) {
        float acc = red[tid] + red[128 + tid];
        out[(size_t)b * M_ + mtile + tid] = acc * 0.01f;   // mean over T=100
    }
}

// ---------------------------------------------------------------------------
// Serial launch (multi-stream overlap regressed twice: R11 +5us, R12 +42us).
// ---------------------------------------------------------------------------
extern "C" void kernel_launch(void* const* d_in, const int* in_sizes, int n_in,
                              void* d_out, int out_size) {
    const float* input  = (const float*)d_in[0];   // [512, 512]
    const float* weight = (const float*)d_in[1];   // [512, 512]
    const float* bias   = (const float*)d_in[2];   // [512]
    float* out = (float*)d_out;                    // [512, 512]

    cudaFuncSetAttribute(gemm_kernel, cudaFuncAttributeMaxDynamicSharedMemorySize, SMEM_GEMM);

    gen_kernel<<<1024, 256>>>(input, 1u);
    wconv_kernel<<<512, 512>>>(weight);
    gemm_kernel<<<dim3(4, 512), 256, SMEM_GEMM>>>(bias, out);
}